// round 15
// baseline (speedup 1.0000x reference)
#include <cuda_runtime.h>
#include <cuda_fp16.h>
#include <cstdint>

#define T_     2048
#define TPAD_  2052
#define P_     64
#define TOUT_  2044
#define NT_    512
#define TILE_  512
#define HALO_  516      // TILE + LAG - 1

// smem byte offsets (two nets per block, 1 block/SM, 16 warps)
#define XBUF_    66048        // 516 rows x 128B
#define SM_X0    0
#define SM_X1    66048
#define SM_W0F   132096       // 40960B W0 fragments (2 nets)
#define SM_W1F   173056       // 8192B W1 fragments (2 nets)
#define SM_BIAS  181248       // 2 x 128 floats
#define SM_RES   182272       // 512 x 2 floats
#define SM_TOTAL 186368       // ~182 KB

// pre-packed weights / pre-converted X (fp16)
__device__ uint4 g_W0h[64 * 20 * 2 * 32];      // [n][s][ntpair][lane]: frag nt0|nt1
__device__ uint2 g_W1f[64 * 4 * 4 * 32];       // [n][f][nt][lane]
__device__ char  g_Xh[16 * TPAD_ * 128];       // [batch][row][128B swizzled fp16]

__device__ __forceinline__ uint32_t pkhf(float a, float b) {
    __half2 t = __floats2half2_rn(a, b);
    return *(uint32_t*)&t;
}
__device__ __forceinline__ float hlo(float v) {   // residual after fp16 round
    return v - __half2float(__float2half_rn(v));
}
__device__ __forceinline__ uint32_t smem_u32(const void* p) {
    uint32_t a;
    asm("{ .reg .u64 t; cvta.to.shared.u64 t, %1; cvt.u32.u64 %0, t; }" : "=r"(a) : "l"(p));
    return a;
}

__device__ __forceinline__ void mma16816(float* d, const uint32_t* a, uint32_t b0, uint32_t b1) {
    asm volatile(
        "mma.sync.aligned.m16n8k16.row.col.f32.f16.f16.f32 "
        "{%0,%1,%2,%3}, {%4,%5,%6,%7}, {%8,%9}, {%0,%1,%2,%3};"
        : "+f"(d[0]), "+f"(d[1]), "+f"(d[2]), "+f"(d[3])
        : "r"(a[0]), "r"(a[1]), "r"(a[2]), "r"(a[3]), "r"(b0), "r"(b1));
}
__device__ __forceinline__ void ldsm4(uint32_t* a, uint32_t addr) {
    asm volatile("ldmatrix.sync.aligned.m8n8.x4.shared.b16 {%0,%1,%2,%3}, [%4];"
        : "=r"(a[0]), "=r"(a[1]), "=r"(a[2]), "=r"(a[3]) : "r"(addr));
}
__device__ __forceinline__ void cpa16(uint32_t dst, const void* src) {
    asm volatile("cp.async.cg.shared.global [%0], [%1], 16;" :: "r"(dst), "l"(src));
}
__device__ __forceinline__ void cpa_commit() {
    asm volatile("cp.async.commit_group;");
}
__device__ __forceinline__ void cpa_wait_all() {
    asm volatile("cp.async.wait_group 0;" ::: "memory");
}

// per-lane ldmatrix address into swizzled [row][64 fp16] tile (128B rows)
__device__ __forceinline__ uint32_t lmAddr(uint32_t buf, int rowBase, int kBase,
                                           int rl, int kl) {
    int row = rowBase + rl;
    int col = kBase + kl;
    return buf + row * 128 + ((col * 2) ^ ((row & 7) << 4));
}

// ---------------- prep: pack weights + pre-convert X (fp16) ----------------
__global__ void prep(const float* __restrict__ X,
                     const float* __restrict__ W0,
                     const float* __restrict__ W1) {
    const int id = blockIdx.x * blockDim.x + threadIdx.x;
    const int stride = gridDim.x * blockDim.x;

    // X -> fp16, swizzled 128B rows, zero-padded rows 2048..2051
    for (int d = id; d < 16 * TPAD_ * 16; d += stride) {
        int q = d & 15;
        int rr = d >> 4;
        int t = rr % TPAD_, bbt = rr / TPAD_;
        float4 v = make_float4(0.f, 0.f, 0.f, 0.f);
        if (t < T_) v = *(const float4*)(X + ((size_t)bbt * T_ + t) * P_ + q * 4);
        uint2 hv = make_uint2(pkhf(v.x, v.y), pkhf(v.z, v.w));
        int off = (q * 8) ^ ((t & 7) << 4);
        *(uint2*)(g_Xh + ((size_t)bbt * TPAD_ + t) * 128 + off) = hv;
    }

    // W0 fragments: single fp16, two nt-fragments packed per uint4
    for (int d = id; d < 64 * 20 * 2 * 32; d += stride) {
        int lane = d & 31;
        int rr = d >> 5;
        int pr = rr & 1; rr >>= 1;
        int s = rr % 20, n = rr / 20;
        int l = s >> 2, cc = s & 3;
        int k0 = (lane & 3) * 2;
        uint4 o;
#pragma unroll
        for (int half = 0; half < 2; ++half) {
            int nt = pr * 2 + half;
            int h = nt * 8 + (lane >> 2);
            float v[4];
#pragma unroll
            for (int j = 0; j < 4; ++j) {
                int k = k0 + ((j >> 1) * 8) + (j & 1);
                v[j] = W0[((n * 32 + h) * 64 + (cc * 16 + k)) * 5 + l];
            }
            if (half == 0) { o.x = pkhf(v[0], v[1]); o.y = pkhf(v[2], v[3]); }
            else           { o.z = pkhf(v[0], v[1]); o.w = pkhf(v[2], v[3]); }
        }
        g_W0h[d] = o;
    }

    // W1 fragments: f0,f1 = hi (i-chunks 0,1), f2,f3 = lo (i-chunks 0,1)
    for (int d = id; d < 64 * 4 * 4 * 32; d += stride) {
        int lane = d & 31;
        int rr = d >> 5;
        int nt = rr & 3; rr >>= 2;
        int f = rr & 3;
        int n = rr >> 2;
        int k0 = (lane & 3) * 2;
        int o = nt * 8 + (lane >> 2);
        int ib = (f & 1) * 16;
        float v[4];
#pragma unroll
        for (int j = 0; j < 4; ++j) {
            int k = k0 + ((j >> 1) * 8) + (j & 1);
            v[j] = W1[(n * 32 + o) * 32 + ib + k];
        }
        if (f >= 2) {
#pragma unroll
            for (int j = 0; j < 4; ++j) v[j] = hlo(v[j]);
        }
        g_W1f[d] = make_uint2(pkhf(v[0], v[1]), pkhf(v[2], v[3]));
    }
}

// ---------------- main: 2 nets, 2x512-row tiles, X double-buffered ----------------
__global__ __launch_bounds__(NT_, 1)
void cmlp_mma(const float* __restrict__ b0,
              const float* __restrict__ b1,
              const float* __restrict__ W2,
              const float* __restrict__ b2,
              float* __restrict__ out) {
    extern __shared__ char sm[];
    const uint32_t sb = smem_u32(sm);
    const int tid = threadIdx.x, warp = tid >> 5, lane = tid & 31;
    const int n0 = blockIdx.x * 2;            // first net of pair
    const int bbt = blockIdx.y >> 1;          // batch
    const int base_t = (blockIdx.y & 1) * 1024;

    // ---- stage W0 + W1 + bias + X tile0 (pure cp.async) ----
    {
        const char* gh = g_Xh + ((size_t)bbt * TPAD_ + base_t) * 128;
        for (int m = tid; m < HALO_ * 8; m += NT_)
            cpa16(sb + SM_X0 + m * 16, gh + m * 16);
        const char* s0 = (const char*)(g_W0h + (size_t)n0 * 1280);
        for (int i = tid; i < 2560; i += NT_)
            cpa16(sb + SM_W0F + i * 16, s0 + i * 16);
        const char* s1 = (const char*)(g_W1f + (size_t)n0 * 512);
        for (int i = tid; i < 512; i += NT_)
            cpa16(sb + SM_W1F + i * 16, s1 + i * 16);
        float* bs = (float*)(sm + SM_BIAS);
        if (tid < 64) {
            int g = tid >> 5, j = tid & 31, n = n0 + g;
            bs[g * 128 + j]      = b0[n * 32 + j];
            bs[g * 128 + 32 + j] = b1[n * 32 + j];
            bs[g * 128 + 64 + j] = W2[n * 32 + j];
            if (j == 0) bs[g * 128 + 96] = b2[n];
        }
        cpa_commit();
        cpa_wait_all();
    }
    __syncthreads();

    const float* bias = (const float*)(sm + SM_BIAS);
    const uint4* W0sA = (const uint4*)(sm + SM_W0F);         // net0: [s][pr][lane]
    const uint4* W0sB = W0sA + 1280;                         // net1
    const uint2* W1f = (const uint2*)(sm + SM_W1F);
    float* res = (float*)(sm + SM_RES);
    const int r = lane >> 2, c0 = (lane & 3) * 2;
    const int rl = lane & 15, kl = (lane >> 4) << 3;   // ldmatrix lane mapping

#pragma unroll 1
    for (int tile = 0; tile < 2; ++tile) {
        const int t0 = base_t + tile * TILE_;
        const uint32_t Xb = sb + (tile ? SM_X1 : SM_X0);

        // prefetch next tile's X into the other buffer (overlapped with compute)
        if (tile == 0) {
            const char* gh = g_Xh + ((size_t)bbt * TPAD_ + t0 + TILE_) * 128;
            for (int m = tid; m < HALO_ * 8; m += NT_)
                cpa16(sb + SM_X1 + m * 16, gh + m * 16);
            cpa_commit();
        }

        // ---- layer 0: warp owns 32 rows, 2 nets x N32, K=320, single fp16 ----
        float acc[2][2][4][4];   // [net][mt][nt][e]
#pragma unroll
        for (int g = 0; g < 2; ++g)
#pragma unroll
            for (int mt = 0; mt < 2; ++mt)
#pragma unroll
                for (int nt = 0; nt < 4; ++nt)
#pragma unroll
                    for (int e = 0; e < 4; ++e)
                        acc[g][mt][nt][e] = bias[g * 128 + nt * 8 + c0 + (e & 1)];

#pragma unroll 1
        for (int s = 0; s < 20; ++s) {
            const int l = s >> 2, cc = s & 3;
            uint4 wa0 = W0sA[(s * 2 + 0) * 32 + lane];
            uint4 wa1 = W0sA[(s * 2 + 1) * 32 + lane];
            uint4 wb0 = W0sB[(s * 2 + 0) * 32 + lane];
            uint4 wb1 = W0sB[(s * 2 + 1) * 32 + lane];
            uint32_t ah[2][4];
#pragma unroll
            for (int mt = 0; mt < 2; ++mt)
                ldsm4(ah[mt], lmAddr(Xb, warp * 32 + mt * 16 + l, cc * 16, rl, kl));
#pragma unroll
            for (int mt = 0; mt < 2; ++mt) {
                mma16816(acc[0][mt][0], ah[mt], wa0.x, wa0.y);
                mma16816(acc[0][mt][1], ah[mt], wa0.z, wa0.w);
                mma16816(acc[0][mt][2], ah[mt], wa1.x, wa1.y);
                mma16816(acc[0][mt][3], ah[mt], wa1.z, wa1.w);
                mma16816(acc[1][mt][0], ah[mt], wb0.x, wb0.y);
                mma16816(acc[1][mt][1], ah[mt], wb0.z, wb0.w);
                mma16816(acc[1][mt][2], ah[mt], wb1.x, wb1.y);
                mma16816(acc[1][mt][3], ah[mt], wb1.z, wb1.w);
            }
        }

        // ---- relu + in-register C-frag -> A-frag conversion ----
        uint32_t af[2][2][2][4];   // [g][mt][kc][j]
#pragma unroll
        for (int g = 0; g < 2; ++g)
#pragma unroll
            for (int mt = 0; mt < 2; ++mt)
#pragma unroll
                for (int kc = 0; kc < 2; ++kc) {
                    const float* a0 = acc[g][mt][2 * kc + 0];
                    const float* a1 = acc[g][mt][2 * kc + 1];
                    af[g][mt][kc][0] = pkhf(fmaxf(a0[0], 0.f), fmaxf(a0[1], 0.f));
                    af[g][mt][kc][1] = pkhf(fmaxf(a0[2], 0.f), fmaxf(a0[3], 0.f));
                    af[g][mt][kc][2] = pkhf(fmaxf(a1[0], 0.f), fmaxf(a1[1], 0.f));
                    af[g][mt][kc][3] = pkhf(fmaxf(a1[2], 0.f), fmaxf(a1[3], 0.f));
                }

        // ---- layer 1: hiH*W1hi + hiH*W1lo (= hiH * W1 exactly), in regs ----
        float acc1[2][2][4][4];
#pragma unroll
        for (int g = 0; g < 2; ++g)
#pragma unroll
            for (int mt = 0; mt < 2; ++mt)
#pragma unroll
                for (int nt = 0; nt < 4; ++nt)
#pragma unroll
                    for (int e = 0; e < 4; ++e)
                        acc1[g][mt][nt][e] = bias[g * 128 + 32 + nt * 8 + c0 + (e & 1)];

#pragma unroll
        for (int f = 0; f < 4; ++f) {          // f0,f1 = W1 hi; f2,f3 = W1 lo
            const int kc = f & 1;
#pragma unroll
            for (int g = 0; g < 2; ++g)
#pragma unroll
                for (int nt = 0; nt < 4; ++nt) {
                    uint2 w = W1f[(g * 16 + f * 4 + nt) * 32 + lane];
#pragma unroll
                    for (int mt = 0; mt < 2; ++mt)
                        mma16816(acc1[g][mt][nt], af[g][mt][kc], w.x, w.y);
                }
        }

        // ---- layer 2: dot with W2, shfl-reduce over lane%4 group ----
#pragma unroll
        for (int g = 0; g < 2; ++g)
#pragma unroll
            for (int mt = 0; mt < 2; ++mt)
#pragma unroll
                for (int half = 0; half < 2; ++half) {
                    float s = 0.f;
#pragma unroll
                    for (int nt = 0; nt < 4; ++nt)
#pragma unroll
                        for (int e = 0; e < 2; ++e) {
                            int c = nt * 8 + c0 + e;
                            s = fmaf(fmaxf(acc1[g][mt][nt][half * 2 + e], 0.f),
                                     bias[g * 128 + 64 + c], s);
                        }
                    s += __shfl_xor_sync(0xFFFFFFFFu, s, 1);
                    s += __shfl_xor_sync(0xFFFFFFFFu, s, 2);
                    if ((lane & 3) == 0)
                        res[(warp * 32 + mt * 16 + r + 8 * half) * 2 + g] =
                            s + bias[g * 128 + 96];
                }
        __syncthreads();

        // ---- store: float2 per timestep (both nets) ----
        {
            int t = t0 + tid;
            if (t < TOUT_)
                *(float2*)(out + ((size_t)bbt * TOUT_ + t) * P_ + n0) =
                    *(const float2*)(res + tid * 2);
        }

        // ---- drain prefetch + make buffer visible before next tile ----
        if (tile == 0) {
            cpa_wait_all();
            __syncthreads();
        }
    }
}

// ---------------- launch ----------------
extern "C" void kernel_launch(void* const* d_in, const int* in_sizes, int n_in,
                              void* d_out, int out_size) {
    const float* X  = (const float*)d_in[0];
    const float* W0 = (const float*)d_in[1];
    const float* b0 = (const float*)d_in[2];
    const float* W1 = (const float*)d_in[3];
    const float* b1 = (const float*)d_in[4];
    const float* W2 = (const float*)d_in[5];
    const float* b2 = (const float*)d_in[6];
    float* out = (float*)d_out;

    cudaFuncSetAttribute(cmlp_mma, cudaFuncAttributeMaxDynamicSharedMemorySize,
                         SM_TOTAL);
    prep<<<1024, 256>>>(X, W0, W1);
    dim3 grid(P_ / 2, 32);   // 32 net-pairs x (16 batches x 2 halves)
    cmlp_mma<<<grid, NT_, SM_TOTAL>>>(b0, b1, W2, b2, out);
}

// round 16
// speedup vs baseline: 1.1184x; 1.1184x over previous
#include <cuda_runtime.h>
#include <cuda_fp16.h>
#include <cstdint>

#define T_     2048
#define TPAD_  2052
#define P_     64
#define TOUT_  2044
#define NT_    256
#define TILE_  256
#define HALO_  260      // TILE + LAG - 1

// smem byte offsets (two nets per block, 2 blocks/SM)
#define SM_X0    0            // X fp16 (260 rows x 128B)
#define SM_W0F   33280        // 40960B W0 fragments (2 nets)
#define SM_W1F   74240        // 8192B W1 fragments (2 nets)
#define SM_BIAS  82432        // 2 x 128 floats (b0|b1|W2|b2)
#define SM_TOTAL 83456        // ~81.5 KB

// pre-packed weights / pre-converted X (fp16)
__device__ uint4 g_W0h[64 * 20 * 2 * 32];      // [n][s][ntpair][lane]: frag nt0|nt1
__device__ uint2 g_W1f[64 * 4 * 4 * 32];       // [n][f][nt][lane]
__device__ char  g_Xh[16 * TPAD_ * 128];       // [batch][row][128B swizzled fp16]

__device__ __forceinline__ uint32_t pkhf(float a, float b) {
    __half2 t = __floats2half2_rn(a, b);
    return *(uint32_t*)&t;
}
__device__ __forceinline__ float hlo(float v) {   // residual after fp16 round
    return v - __half2float(__float2half_rn(v));
}
__device__ __forceinline__ uint32_t smem_u32(const void* p) {
    uint32_t a;
    asm("{ .reg .u64 t; cvta.to.shared.u64 t, %1; cvt.u32.u64 %0, t; }" : "=r"(a) : "l"(p));
    return a;
}

__device__ __forceinline__ void mma16816(float* d, const uint32_t* a, uint32_t b0, uint32_t b1) {
    asm volatile(
        "mma.sync.aligned.m16n8k16.row.col.f32.f16.f16.f32 "
        "{%0,%1,%2,%3}, {%4,%5,%6,%7}, {%8,%9}, {%0,%1,%2,%3};"
        : "+f"(d[0]), "+f"(d[1]), "+f"(d[2]), "+f"(d[3])
        : "r"(a[0]), "r"(a[1]), "r"(a[2]), "r"(a[3]), "r"(b0), "r"(b1));
}
__device__ __forceinline__ void ldsm4(uint32_t* a, uint32_t addr) {
    asm volatile("ldmatrix.sync.aligned.m8n8.x4.shared.b16 {%0,%1,%2,%3}, [%4];"
        : "=r"(a[0]), "=r"(a[1]), "=r"(a[2]), "=r"(a[3]) : "r"(addr));
}
__device__ __forceinline__ void cpa16(uint32_t dst, const void* src) {
    asm volatile("cp.async.cg.shared.global [%0], [%1], 16;" :: "r"(dst), "l"(src));
}
__device__ __forceinline__ void cpa_commit() {
    asm volatile("cp.async.commit_group;");
}
template <int N>
__device__ __forceinline__ void cpa_wait() {
    asm volatile("cp.async.wait_group %0;" :: "n"(N) : "memory");
}

// per-lane ldmatrix address into swizzled [row][64 fp16] tile (128B rows)
__device__ __forceinline__ uint32_t lmAddr(uint32_t buf, int rowBase, int kBase,
                                           int rl, int kl) {
    int row = rowBase + rl;
    int col = kBase + kl;
    return buf + row * 128 + ((col * 2) ^ ((row & 7) << 4));
}

// ---------------- prep: pack weights + pre-convert X (fp16) ----------------
__global__ void prep(const float* __restrict__ X,
                     const float* __restrict__ W0,
                     const float* __restrict__ W1) {
    const int id = blockIdx.x * blockDim.x + threadIdx.x;
    const int stride = gridDim.x * blockDim.x;

    // X -> fp16, swizzled 128B rows, zero-padded rows 2048..2051
    for (int d = id; d < 16 * TPAD_ * 16; d += stride) {
        int q = d & 15;
        int rr = d >> 4;
        int t = rr % TPAD_, bbt = rr / TPAD_;
        float4 v = make_float4(0.f, 0.f, 0.f, 0.f);
        if (t < T_) v = *(const float4*)(X + ((size_t)bbt * T_ + t) * P_ + q * 4);
        uint2 hv = make_uint2(pkhf(v.x, v.y), pkhf(v.z, v.w));
        int off = (q * 8) ^ ((t & 7) << 4);
        *(uint2*)(g_Xh + ((size_t)bbt * TPAD_ + t) * 128 + off) = hv;
    }

    // W0 fragments: single fp16, two nt-fragments packed per uint4
    for (int d = id; d < 64 * 20 * 2 * 32; d += stride) {
        int lane = d & 31;
        int rr = d >> 5;
        int pr = rr & 1; rr >>= 1;
        int s = rr % 20, n = rr / 20;
        int l = s >> 2, cc = s & 3;
        int k0 = (lane & 3) * 2;
        uint4 o;
#pragma unroll
        for (int half = 0; half < 2; ++half) {
            int nt = pr * 2 + half;
            int h = nt * 8 + (lane >> 2);
            float v[4];
#pragma unroll
            for (int j = 0; j < 4; ++j) {
                int k = k0 + ((j >> 1) * 8) + (j & 1);
                v[j] = W0[((n * 32 + h) * 64 + (cc * 16 + k)) * 5 + l];
            }
            if (half == 0) { o.x = pkhf(v[0], v[1]); o.y = pkhf(v[2], v[3]); }
            else           { o.z = pkhf(v[0], v[1]); o.w = pkhf(v[2], v[3]); }
        }
        g_W0h[d] = o;
    }

    // W1 fragments: f0,f1 = hi (i-chunks 0,1), f2,f3 = lo (i-chunks 0,1)
    for (int d = id; d < 64 * 4 * 4 * 32; d += stride) {
        int lane = d & 31;
        int rr = d >> 5;
        int nt = rr & 3; rr >>= 2;
        int f = rr & 3;
        int n = rr >> 2;
        int k0 = (lane & 3) * 2;
        int o = nt * 8 + (lane >> 2);
        int ib = (f & 1) * 16;
        float v[4];
#pragma unroll
        for (int j = 0; j < 4; ++j) {
            int k = k0 + ((j >> 1) * 8) + (j & 1);
            v[j] = W1[(n * 32 + o) * 32 + ib + k];
        }
        if (f >= 2) {
#pragma unroll
            for (int j = 0; j < 4; ++j) v[j] = hlo(v[j]);
        }
        g_W1f[d] = make_uint2(pkhf(v[0], v[1]), pkhf(v[2], v[3]));
    }
}

// ---------------- main: 2 nets per block, split staging, direct-STG epilogue ----------------
__global__ __launch_bounds__(NT_, 2)
void cmlp_mma(const float* __restrict__ b0,
              const float* __restrict__ b1,
              const float* __restrict__ W2,
              const float* __restrict__ b2,
              float* __restrict__ out) {
    extern __shared__ char sm[];
    const uint32_t sb = smem_u32(sm);
    const int tid = threadIdx.x, warp = tid >> 5, lane = tid & 31;
    const int n0 = blockIdx.x * 2;  // first net of pair
    const int p = blockIdx.y;
    const int bbt = p >> 3;
    const int t0 = (p & 7) * TILE_;

    // ---- staging: group0 = X + W0 steps 0..9 ; group1 = W0 rest + W1 ----
    {
        const char* gh = g_Xh + ((size_t)bbt * TPAD_ + t0) * 128;
        for (int m = tid; m < HALO_ * 8; m += NT_)
            cpa16(sb + SM_X0 + m * 16, gh + m * 16);
        const char* s0 = (const char*)(g_W0h + (size_t)n0 * 1280);
        for (int i = tid; i < 640; i += NT_) {
            cpa16(sb + SM_W0F + i * 16, s0 + i * 16);                        // net A early
            cpa16(sb + SM_W0F + (1280 + i) * 16, s0 + (1280 + i) * 16);      // net B early
        }
        cpa_commit();
        for (int i = 640 + tid; i < 1280; i += NT_) {
            cpa16(sb + SM_W0F + i * 16, s0 + i * 16);                        // net A late
            cpa16(sb + SM_W0F + (1280 + i) * 16, s0 + (1280 + i) * 16);      // net B late
        }
        const char* s1 = (const char*)(g_W1f + (size_t)n0 * 512);
        for (int i = tid; i < 512; i += NT_)
            cpa16(sb + SM_W1F + i * 16, s1 + i * 16);
        cpa_commit();
        float* bs = (float*)(sm + SM_BIAS);
        if (tid < 64) {
            int g = tid >> 5, j = tid & 31, n = n0 + g;
            bs[g * 128 + j]      = b0[n * 32 + j];
            bs[g * 128 + 32 + j] = b1[n * 32 + j];
            bs[g * 128 + 64 + j] = W2[n * 32 + j];
            if (j == 0) bs[g * 128 + 96] = b2[n];
        }
        cpa_wait<1>();   // group0 (X + early W0) landed
    }
    __syncthreads();

    const float* bias = (const float*)(sm + SM_BIAS);
    const uint32_t Xhi = sb + SM_X0;
    const uint4* W0sA = (const uint4*)(sm + SM_W0F);         // net0: [s][pr][lane]
    const uint4* W0sB = W0sA + 1280;                         // net1
    const uint2* W1f = (const uint2*)(sm + SM_W1F);
    const int r = lane >> 2, c0 = (lane & 3) * 2;
    const int rl = lane & 15, kl = (lane >> 4) << 3;   // ldmatrix lane mapping

    // ---- layer 0: warp owns 32 rows, 2 nets x N32, K=320, single fp16 ----
    float acc[2][2][4][4];   // [net][mt][nt][e]
#pragma unroll
    for (int g = 0; g < 2; ++g)
#pragma unroll
        for (int mt = 0; mt < 2; ++mt)
#pragma unroll
            for (int nt = 0; nt < 4; ++nt)
#pragma unroll
                for (int e = 0; e < 4; ++e)
                    acc[g][mt][nt][e] = bias[g * 128 + nt * 8 + c0 + (e & 1)];

    auto step = [&](int s) {
        const int l = s >> 2, cc = s & 3;
        uint4 wa0 = W0sA[(s * 2 + 0) * 32 + lane];
        uint4 wa1 = W0sA[(s * 2 + 1) * 32 + lane];
        uint4 wb0 = W0sB[(s * 2 + 0) * 32 + lane];
        uint4 wb1 = W0sB[(s * 2 + 1) * 32 + lane];
        uint32_t ah[2][4];
#pragma unroll
        for (int mt = 0; mt < 2; ++mt)
            ldsm4(ah[mt], lmAddr(Xhi, warp * 32 + mt * 16 + l, cc * 16, rl, kl));
#pragma unroll
        for (int mt = 0; mt < 2; ++mt) {
            mma16816(acc[0][mt][0], ah[mt], wa0.x, wa0.y);
            mma16816(acc[0][mt][1], ah[mt], wa0.z, wa0.w);
            mma16816(acc[0][mt][2], ah[mt], wa1.x, wa1.y);
            mma16816(acc[0][mt][3], ah[mt], wa1.z, wa1.w);
            mma16816(acc[1][mt][0], ah[mt], wb0.x, wb0.y);
            mma16816(acc[1][mt][1], ah[mt], wb0.z, wb0.w);
            mma16816(acc[1][mt][2], ah[mt], wb1.x, wb1.y);
            mma16816(acc[1][mt][3], ah[mt], wb1.z, wb1.w);
        }
    };

#pragma unroll 1
    for (int s = 0; s < 10; ++s) step(s);
    cpa_wait<0>();                 // group1 (late W0 + W1) landed
    __syncthreads();
#pragma unroll 1
    for (int s = 10; s < 20; ++s) step(s);

    // ---- relu + in-register fragment conversion: C-frag -> A-frag ----
    uint32_t af[2][2][2][4];   // [g][mt][kc][j]
#pragma unroll
    for (int g = 0; g < 2; ++g)
#pragma unroll
        for (int mt = 0; mt < 2; ++mt)
#pragma unroll
            for (int kc = 0; kc < 2; ++kc) {
                const float* a0 = acc[g][mt][2 * kc + 0];
                const float* a1 = acc[g][mt][2 * kc + 1];
                af[g][mt][kc][0] = pkhf(fmaxf(a0[0], 0.f), fmaxf(a0[1], 0.f));
                af[g][mt][kc][1] = pkhf(fmaxf(a0[2], 0.f), fmaxf(a0[3], 0.f));
                af[g][mt][kc][2] = pkhf(fmaxf(a1[0], 0.f), fmaxf(a1[1], 0.f));
                af[g][mt][kc][3] = pkhf(fmaxf(a1[2], 0.f), fmaxf(a1[3], 0.f));
            }

    // ---- layer 1: hiH*W1hi + hiH*W1lo (= hiH * W1 exactly), in registers ----
    float acc1[2][2][4][4];
#pragma unroll
    for (int g = 0; g < 2; ++g)
#pragma unroll
        for (int mt = 0; mt < 2; ++mt)
#pragma unroll
            for (int nt = 0; nt < 4; ++nt)
#pragma unroll
                for (int e = 0; e < 4; ++e)
                    acc1[g][mt][nt][e] = bias[g * 128 + 32 + nt * 8 + c0 + (e & 1)];

#pragma unroll
    for (int f = 0; f < 4; ++f) {          // f0,f1 = W1 hi; f2,f3 = W1 lo
        const int kc = f & 1;              // matching H i-chunk
#pragma unroll
        for (int g = 0; g < 2; ++g)
#pragma unroll
            for (int nt = 0; nt < 4; ++nt) {
                uint2 w = W1f[(g * 16 + f * 4 + nt) * 32 + lane];
#pragma unroll
                for (int mt = 0; mt < 2; ++mt)
                    mma16816(acc1[g][mt][nt], af[g][mt][kc], w.x, w.y);
            }
    }

    // ---- layer 2: dot with W2, shfl-reduce, direct float2 store ----
#pragma unroll
    for (int mt = 0; mt < 2; ++mt)
#pragma unroll
        for (int half = 0; half < 2; ++half) {
            float sg[2];
#pragma unroll
            for (int g = 0; g < 2; ++g) {
                float s = 0.f;
#pragma unroll
                for (int nt = 0; nt < 4; ++nt)
#pragma unroll
                    for (int e = 0; e < 2; ++e) {
                        int c = nt * 8 + c0 + e;
                        s = fmaf(fmaxf(acc1[g][mt][nt][half * 2 + e], 0.f),
                                 bias[g * 128 + 64 + c], s);
                    }
                s += __shfl_xor_sync(0xFFFFFFFFu, s, 1);
                s += __shfl_xor_sync(0xFFFFFFFFu, s, 2);
                sg[g] = s + bias[g * 128 + 96];
            }
            if ((lane & 3) == 0) {
                int t = t0 + warp * 32 + mt * 16 + r + 8 * half;
                if (t < TOUT_)
                    *(float2*)(out + ((size_t)bbt * TOUT_ + t) * P_ + n0) =
                        make_float2(sg[0], sg[1]);
            }
        }
}

// ---------------- launch ----------------
extern "C" void kernel_launch(void* const* d_in, const int* in_sizes, int n_in,
                              void* d_out, int out_size) {
    const float* X  = (const float*)d_in[0];
    const float* W0 = (const float*)d_in[1];
    const float* b0 = (const float*)d_in[2];
    const float* W1 = (const float*)d_in[3];
    const float* b1 = (const float*)d_in[4];
    const float* W2 = (const float*)d_in[5];
    const float* b2 = (const float*)d_in[6];
    float* out = (float*)d_out;

    cudaFuncSetAttribute(cmlp_mma, cudaFuncAttributeMaxDynamicSharedMemorySize,
                         SM_TOTAL);
    prep<<<1024, 256>>>(X, W0, W1);
    dim3 grid(P_ / 2, 128);   // 32 net-pairs x (8 tiles x 16 batches)
    cmlp_mma<<<grid, NT_, SM_TOTAL>>>(b0, b1, W2, b2, out);
}

// round 17
// speedup vs baseline: 1.1752x; 1.0507x over previous
#include <cuda_runtime.h>
#include <cuda_fp16.h>
#include <cstdint>

#define T_     2048
#define TPAD_  2052
#define P_     64
#define TOUT_  2044
#define NT_    256
#define TILE_  256
#define HALO_  260      // TILE + LAG - 1

// smem byte offsets (two nets, two X buffers, 2 blocks/SM)
#define SM_X0    0            // X fp16 tile0 (260 rows x 128B)
#define SM_X1    33280        // X fp16 tile1
#define SM_W0F   66560        // 40960B W0 fragments (2 nets)
#define SM_W1F   107520       // 4096B W1 hi fragments (2 nets)
#define SM_BIAS  111616       // 2 x 128 floats (b0|b1|W2|b2)
#define SM_TOTAL 112640       // 110 KB

// pre-packed weights / pre-converted X (fp16)
__device__ uint4 g_W0h[64 * 20 * 2 * 32];      // [n][s][ntpair][lane]: frag nt0|nt1
__device__ uint2 g_W1f[64 * 4 * 4 * 32];       // [n][f][nt][lane] (f0,f1=hi used)
__device__ char  g_Xh[16 * TPAD_ * 128];       // [batch][row][128B swizzled fp16]

__device__ __forceinline__ uint32_t pkhf(float a, float b) {
    __half2 t = __floats2half2_rn(a, b);
    return *(uint32_t*)&t;
}
__device__ __forceinline__ float hlo(float v) {   // residual after fp16 round
    return v - __half2float(__float2half_rn(v));
}
__device__ __forceinline__ uint32_t smem_u32(const void* p) {
    uint32_t a;
    asm("{ .reg .u64 t; cvta.to.shared.u64 t, %1; cvt.u32.u64 %0, t; }" : "=r"(a) : "l"(p));
    return a;
}

__device__ __forceinline__ void mma16816(float* d, const uint32_t* a, uint32_t b0, uint32_t b1) {
    asm volatile(
        "mma.sync.aligned.m16n8k16.row.col.f32.f16.f16.f32 "
        "{%0,%1,%2,%3}, {%4,%5,%6,%7}, {%8,%9}, {%0,%1,%2,%3};"
        : "+f"(d[0]), "+f"(d[1]), "+f"(d[2]), "+f"(d[3])
        : "r"(a[0]), "r"(a[1]), "r"(a[2]), "r"(a[3]), "r"(b0), "r"(b1));
}
__device__ __forceinline__ void ldsm4(uint32_t* a, uint32_t addr) {
    asm volatile("ldmatrix.sync.aligned.m8n8.x4.shared.b16 {%0,%1,%2,%3}, [%4];"
        : "=r"(a[0]), "=r"(a[1]), "=r"(a[2]), "=r"(a[3]) : "r"(addr));
}
__device__ __forceinline__ void cpa16(uint32_t dst, const void* src) {
    asm volatile("cp.async.cg.shared.global [%0], [%1], 16;" :: "r"(dst), "l"(src));
}
__device__ __forceinline__ void cpa_commit() {
    asm volatile("cp.async.commit_group;");
}
template <int N>
__device__ __forceinline__ void cpa_wait() {
    asm volatile("cp.async.wait_group %0;" :: "n"(N) : "memory");
}

// per-lane ldmatrix address into swizzled [row][64 fp16] tile (128B rows)
__device__ __forceinline__ uint32_t lmAddr(uint32_t buf, int rowBase, int kBase,
                                           int rl, int kl) {
    int row = rowBase + rl;
    int col = kBase + kl;
    return buf + row * 128 + ((col * 2) ^ ((row & 7) << 4));
}

// ---------------- prep: pack weights + pre-convert X (fp16) ----------------
__global__ void prep(const float* __restrict__ X,
                     const float* __restrict__ W0,
                     const float* __restrict__ W1) {
    const int id = blockIdx.x * blockDim.x + threadIdx.x;
    const int stride = gridDim.x * blockDim.x;

    // X -> fp16, swizzled 128B rows, zero-padded rows 2048..2051
    for (int d = id; d < 16 * TPAD_ * 16; d += stride) {
        int q = d & 15;
        int rr = d >> 4;
        int t = rr % TPAD_, bbt = rr / TPAD_;
        float4 v = make_float4(0.f, 0.f, 0.f, 0.f);
        if (t < T_) v = *(const float4*)(X + ((size_t)bbt * T_ + t) * P_ + q * 4);
        uint2 hv = make_uint2(pkhf(v.x, v.y), pkhf(v.z, v.w));
        int off = (q * 8) ^ ((t & 7) << 4);
        *(uint2*)(g_Xh + ((size_t)bbt * TPAD_ + t) * 128 + off) = hv;
    }

    // W0 fragments: single fp16, two nt-fragments packed per uint4
    for (int d = id; d < 64 * 20 * 2 * 32; d += stride) {
        int lane = d & 31;
        int rr = d >> 5;
        int pr = rr & 1; rr >>= 1;
        int s = rr % 20, n = rr / 20;
        int l = s >> 2, cc = s & 3;
        int k0 = (lane & 3) * 2;
        uint4 o;
#pragma unroll
        for (int half = 0; half < 2; ++half) {
            int nt = pr * 2 + half;
            int h = nt * 8 + (lane >> 2);
            float v[4];
#pragma unroll
            for (int j = 0; j < 4; ++j) {
                int k = k0 + ((j >> 1) * 8) + (j & 1);
                v[j] = W0[((n * 32 + h) * 64 + (cc * 16 + k)) * 5 + l];
            }
            if (half == 0) { o.x = pkhf(v[0], v[1]); o.y = pkhf(v[2], v[3]); }
            else           { o.z = pkhf(v[0], v[1]); o.w = pkhf(v[2], v[3]); }
        }
        g_W0h[d] = o;
    }

    // W1 fragments: f0,f1 = hi (i-chunks 0,1); f2,f3 legacy lo (unused)
    for (int d = id; d < 64 * 4 * 4 * 32; d += stride) {
        int lane = d & 31;
        int rr = d >> 5;
        int nt = rr & 3; rr >>= 2;
        int f = rr & 3;
        int n = rr >> 2;
        int k0 = (lane & 3) * 2;
        int o = nt * 8 + (lane >> 2);
        int ib = (f & 1) * 16;
        float v[4];
#pragma unroll
        for (int j = 0; j < 4; ++j) {
            int k = k0 + ((j >> 1) * 8) + (j & 1);
            v[j] = W1[(n * 32 + o) * 32 + ib + k];
        }
        if (f >= 2) {
#pragma unroll
            for (int j = 0; j < 4; ++j) v[j] = hlo(v[j]);
        }
        g_W1f[d] = make_uint2(pkhf(v[0], v[1]), pkhf(v[2], v[3]));
    }
}

// ---------------- main: 2 nets, 2 tiles/block, X double-buffered ----------------
__global__ __launch_bounds__(NT_, 2)
void cmlp_mma(const float* __restrict__ b0,
              const float* __restrict__ b1,
              const float* __restrict__ W2,
              const float* __restrict__ b2,
              float* __restrict__ out) {
    extern __shared__ char sm[];
    const uint32_t sb = smem_u32(sm);
    const int tid = threadIdx.x, warp = tid >> 5, lane = tid & 31;
    const int n0 = blockIdx.x * 2;            // first net of pair
    const int bbt = blockIdx.y >> 2;          // batch
    const int base_t = (blockIdx.y & 3) * 512;

    // ---- stage X tile0 + W0 + W1(hi) + bias ----
    {
        const char* gh = g_Xh + ((size_t)bbt * TPAD_ + base_t) * 128;
        for (int m = tid; m < HALO_ * 8; m += NT_)
            cpa16(sb + SM_X0 + m * 16, gh + m * 16);
        const char* s0 = (const char*)(g_W0h + (size_t)n0 * 1280);
        for (int i = tid; i < 2560; i += NT_)
            cpa16(sb + SM_W0F + i * 16, s0 + i * 16);
        const char* s1 = (const char*)(g_W1f + (size_t)n0 * 512);
        if (tid < 256) {
            int g = tid >> 7, j = tid & 127;                  // 16B chunk within net
            cpa16(sb + SM_W1F + tid * 16, s1 + g * 4096 + j * 16);
        }
        float* bs = (float*)(sm + SM_BIAS);
        if (tid < 64) {
            int g = tid >> 5, j = tid & 31, n = n0 + g;
            bs[g * 128 + j]      = b0[n * 32 + j];
            bs[g * 128 + 32 + j] = b1[n * 32 + j];
            bs[g * 128 + 64 + j] = W2[n * 32 + j];
            if (j == 0) bs[g * 128 + 96] = b2[n];
        }
        cpa_commit();
        cpa_wait<0>();
    }
    __syncthreads();

    const float* bias = (const float*)(sm + SM_BIAS);
    const uint4* W0sA = (const uint4*)(sm + SM_W0F);         // net0: [s][pr][lane]
    const uint4* W0sB = W0sA + 1280;                         // net1
    const uint2* W1f = (const uint2*)(sm + SM_W1F);          // [g][f][nt][lane]
    const int r = lane >> 2, c0 = (lane & 3) * 2;
    const int rl = lane & 15, kl = (lane >> 4) << 3;   // ldmatrix lane mapping

#pragma unroll 1
    for (int tile = 0; tile < 2; ++tile) {
        const int t0 = base_t + tile * TILE_;
        const uint32_t Xb = sb + (tile ? SM_X1 : SM_X0);

        // prefetch tile1's X during tile0 compute
        if (tile == 0) {
            const char* gh = g_Xh + ((size_t)bbt * TPAD_ + t0 + TILE_) * 128;
            for (int m = tid; m < HALO_ * 8; m += NT_)
                cpa16(sb + SM_X1 + m * 16, gh + m * 16);
            cpa_commit();
        }

        // ---- layer 0: warp owns 32 rows, 2 nets x N32, K=320, single fp16 ----
        float acc[2][2][4][4];   // [net][mt][nt][e]
#pragma unroll
        for (int g = 0; g < 2; ++g)
#pragma unroll
            for (int mt = 0; mt < 2; ++mt)
#pragma unroll
                for (int nt = 0; nt < 4; ++nt)
#pragma unroll
                    for (int e = 0; e < 4; ++e)
                        acc[g][mt][nt][e] = bias[g * 128 + nt * 8 + c0 + (e & 1)];

#pragma unroll 1
        for (int s = 0; s < 20; ++s) {
            const int l = s >> 2, cc = s & 3;
            uint4 wa0 = W0sA[(s * 2 + 0) * 32 + lane];
            uint4 wa1 = W0sA[(s * 2 + 1) * 32 + lane];
            uint4 wb0 = W0sB[(s * 2 + 0) * 32 + lane];
            uint4 wb1 = W0sB[(s * 2 + 1) * 32 + lane];
            uint32_t ah[2][4];
#pragma unroll
            for (int mt = 0; mt < 2; ++mt)
                ldsm4(ah[mt], lmAddr(Xb, warp * 32 + mt * 16 + l, cc * 16, rl, kl));
#pragma unroll
            for (int mt = 0; mt < 2; ++mt) {
                mma16816(acc[0][mt][0], ah[mt], wa0.x, wa0.y);
                mma16816(acc[0][mt][1], ah[mt], wa0.z, wa0.w);
                mma16816(acc[0][mt][2], ah[mt], wa1.x, wa1.y);
                mma16816(acc[0][mt][3], ah[mt], wa1.z, wa1.w);
                mma16816(acc[1][mt][0], ah[mt], wb0.x, wb0.y);
                mma16816(acc[1][mt][1], ah[mt], wb0.z, wb0.w);
                mma16816(acc[1][mt][2], ah[mt], wb1.x, wb1.y);
                mma16816(acc[1][mt][3], ah[mt], wb1.z, wb1.w);
            }
        }

        // ---- relu + in-register C-frag -> A-frag conversion ----
        uint32_t af[2][2][2][4];   // [g][mt][kc][j]
#pragma unroll
        for (int g = 0; g < 2; ++g)
#pragma unroll
            for (int mt = 0; mt < 2; ++mt)
#pragma unroll
                for (int kc = 0; kc < 2; ++kc) {
                    const float* a0 = acc[g][mt][2 * kc + 0];
                    const float* a1 = acc[g][mt][2 * kc + 1];
                    af[g][mt][kc][0] = pkhf(fmaxf(a0[0], 0.f), fmaxf(a0[1], 0.f));
                    af[g][mt][kc][1] = pkhf(fmaxf(a0[2], 0.f), fmaxf(a0[3], 0.f));
                    af[g][mt][kc][2] = pkhf(fmaxf(a1[0], 0.f), fmaxf(a1[1], 0.f));
                    af[g][mt][kc][3] = pkhf(fmaxf(a1[2], 0.f), fmaxf(a1[3], 0.f));
                }

        // ---- layer 1: hiH * W1hi (single product), in registers ----
        float acc1[2][2][4][4];
#pragma unroll
        for (int g = 0; g < 2; ++g)
#pragma unroll
            for (int mt = 0; mt < 2; ++mt)
#pragma unroll
                for (int nt = 0; nt < 4; ++nt)
#pragma unroll
                    for (int e = 0; e < 4; ++e)
                        acc1[g][mt][nt][e] = bias[g * 128 + 32 + nt * 8 + c0 + (e & 1)];

#pragma unroll
        for (int f = 0; f < 2; ++f) {          // W1 hi fragments only
            const int kc = f;
#pragma unroll
            for (int g = 0; g < 2; ++g)
#pragma unroll
                for (int nt = 0; nt < 4; ++nt) {
                    uint2 w = W1f[g * 256 + f * 128 + nt * 32 + lane];
#pragma unroll
                    for (int mt = 0; mt < 2; ++mt)
                        mma16816(acc1[g][mt][nt], af[g][mt][kc], w.x, w.y);
                }
        }

        // ---- layer 2: dot with W2, shfl-reduce, direct float2 store ----
#pragma unroll
        for (int mt = 0; mt < 2; ++mt)
#pragma unroll
            for (int half = 0; half < 2; ++half) {
                float sg[2];
#pragma unroll
                for (int g = 0; g < 2; ++g) {
                    float s = 0.f;
#pragma unroll
                    for (int nt = 0; nt < 4; ++nt)
#pragma unroll
                        for (int e = 0; e < 2; ++e) {
                            int c = nt * 8 + c0 + e;
                            s = fmaf(fmaxf(acc1[g][mt][nt][half * 2 + e], 0.f),
                                     bias[g * 128 + 64 + c], s);
                        }
                    s += __shfl_xor_sync(0xFFFFFFFFu, s, 1);
                    s += __shfl_xor_sync(0xFFFFFFFFu, s, 2);
                    sg[g] = s + bias[g * 128 + 96];
                }
                if ((lane & 3) == 0) {
                    int t = t0 + warp * 32 + mt * 16 + r + 8 * half;
                    if (t < TOUT_)
                        *(float2*)(out + ((size_t)bbt * TOUT_ + t) * P_ + n0) =
                            make_float2(sg[0], sg[1]);
                }
            }

        // drain tile1 prefetch before using it
        if (tile == 0) {
            cpa_wait<0>();
            __syncthreads();
        }
    }
}

// ---------------- launch ----------------
extern "C" void kernel_launch(void* const* d_in, const int* in_sizes, int n_in,
                              void* d_out, int out_size) {
    const float* X  = (const float*)d_in[0];
    const float* W0 = (const float*)d_in[1];
    const float* b0 = (const float*)d_in[2];
    const float* W1 = (const float*)d_in[3];
    const float* b1 = (const float*)d_in[4];
    const float* W2 = (const float*)d_in[5];
    const float* b2 = (const float*)d_in[6];
    float* out = (float*)d_out;

    cudaFuncSetAttribute(cmlp_mma, cudaFuncAttributeMaxDynamicSharedMemorySize,
                         SM_TOTAL);
    prep<<<1024, 256>>>(X, W0, W1);
    dim3 grid(P_ / 2, 64);   // 32 net-pairs x (16 batches x 4 tile-pairs)
    cmlp_mma<<<grid, NT_, SM_TOTAL>>>(b0, b1, W2, b2, out);
}